// round 13
// baseline (speedup 1.0000x reference)
#include <cuda_runtime.h>

#define NTOK 8192
#define DIM 128
#define ODIM 128
#define THREADS 256
#define OT 2
#define TOKPT 4

typedef unsigned long long u64;

__device__ float g_xnT[DIM * NTOK];   // transposed: [d][n]
__device__ float2 g_musv[NTOK];

__device__ __forceinline__ float2 ffma2(float2 a, float2 b, float2 c) {
    float2 d;
    asm("fma.rn.f32x2 %0, %1, %2, %3;"
        : "=l"(reinterpret_cast<u64&>(d))
        : "l"(reinterpret_cast<u64 const&>(a)),
          "l"(reinterpret_cast<u64 const&>(b)),
          "l"(reinterpret_cast<u64 const&>(c)));
    return d;
}
__device__ __forceinline__ float2 fmul2(float2 a, float2 b) {
    float2 d;
    asm("mul.rn.f32x2 %0, %1, %2;"
        : "=l"(reinterpret_cast<u64&>(d))
        : "l"(reinterpret_cast<u64 const&>(a)),
          "l"(reinterpret_cast<u64 const&>(b)));
    return d;
}
__device__ __forceinline__ float2 fadd2(float2 a, float2 b) {
    float2 d;
    asm("add.rn.f32x2 %0, %1, %2;"
        : "=l"(reinterpret_cast<u64&>(d))
        : "l"(reinterpret_cast<u64 const&>(a)),
          "l"(reinterpret_cast<u64 const&>(b)));
    return d;
}
__device__ __forceinline__ float ex2f(float a) {
    float r; asm("ex2.approx.ftz.f32 %0, %1;" : "=f"(r) : "f"(a)); return r;
}

// ---------------- Kernel 1: LayerNorm + transpose (warp per token) ----------------
__global__ void ln_kernel(const float* __restrict__ x,
                          const float* __restrict__ gamma,
                          const float* __restrict__ beta) {
    __shared__ float sX[8][DIM];
    const int tok0 = blockIdx.x * 8;
    const int w = threadIdx.x >> 5;
    const int lane = threadIdx.x & 31;
    const int token = tok0 + w;

    float4 v = ((const float4*)(x + (size_t)token * DIM))[lane];
    float s = (v.x + v.y) + (v.z + v.w);
    #pragma unroll
    for (int off = 16; off; off >>= 1) s += __shfl_xor_sync(~0u, s, off);
    float mu = s * (1.0f / DIM);
    float dx = v.x - mu, dy = v.y - mu, dz = v.z - mu, dw = v.w - mu;
    float q = (dx * dx + dy * dy) + (dz * dz + dw * dw);
    #pragma unroll
    for (int off = 16; off; off >>= 1) q += __shfl_xor_sync(~0u, q, off);
    float ve = q * (1.0f / DIM) + 1e-5f;
    float r = rsqrtf(ve);
    float4 g = ((const float4*)gamma)[lane];
    float4 b = ((const float4*)beta)[lane];
    float4 o;
    o.x = fmaf(dx * r, g.x, b.x);
    o.y = fmaf(dy * r, g.y, b.y);
    o.z = fmaf(dz * r, g.z, b.z);
    o.w = fmaf(dw * r, g.w, b.w);
    ((float4*)&sX[w][0])[lane] = o;
    if (lane == 0) g_musv[token] = make_float2(mu, ve * r);
    __syncthreads();

    const int d = threadIdx.x >> 1;
    const int h = threadIdx.x & 1;
    float4 val;
    val.x = sX[4 * h + 0][d];
    val.y = sX[4 * h + 1][d];
    val.z = sX[4 * h + 2][d];
    val.w = sX[4 * h + 3][d];
    *((float4*)(g_xnT + (size_t)d * NTOK + tok0 + 4 * h)) = val;
}

// ---------------- Kernel 2: fused wavelet + base, OT=2 TOKPT=4 ----------------
// T-form: y = xn + T (T=-t), m = H + a*y^2 (a=-H/s^2, H=1/(2 ln2))
//   wavelet contribution = CP * m * 2^m,  CP = -C*ww/(H*2^H) = -0.7292730*ww
// base in xn-domain: b_o = sv*(acc_o - K1_o) + mu*K2_o  (W'=bw/gamma)
__global__ __launch_bounds__(THREADS, 3)
void wave_kernel(const float* __restrict__ scale,
                 const float* __restrict__ trans,
                 const float* __restrict__ ww,
                 const float* __restrict__ bw,
                 const float* __restrict__ gamma,
                 const float* __restrict__ beta,
                 float* __restrict__ out) {
    __shared__ float4 sT [OT][DIM / 4];
    __shared__ float4 sA [OT][DIM / 4];
    __shared__ float4 sCP[OT][DIM / 4];
    __shared__ float4 sW [OT][DIM / 4];
    __shared__ float  sK1[OT], sK2[OT];

    const int o0 = blockIdx.y * OT;
    const int tid = threadIdx.x;
    const float H = 0.72134752f;
    const float2 H2 = make_float2(H, H);

    // ---- fold params (OT*DIM = 256 elements, one per thread) ----
    {
        int i = tid;
        int gi = o0 * DIM + i;
        int d = i & (DIM - 1);
        float sc = scale[gi];
        float sp = (sc > 20.0f) ? sc : log1pf(expf(sc));
        float s = sp + 0.1f;
        ((float*)sT)[i]  = -trans[gi];
        ((float*)sA)[i]  = -H / (s * s);
        ((float*)sCP)[i] = -0.7292730f * ww[gi];
        ((float*)sW)[i]  = bw[gi] / gamma[d];
    }
    __syncthreads();

    // ---- K1, K2 per o: warp w (w < OT) reduces o=w ----
    {
        int w = tid >> 5, lane = tid & 31;
        if (w < OT) {
            float4 wp = sW[w][lane];
            float4 g4 = ((const float4*)gamma)[lane];
            float4 b4 = ((const float4*)beta)[lane];
            float k1 = (wp.x * b4.x + wp.y * b4.y) + (wp.z * b4.z + wp.w * b4.w);
            float k2 = (wp.x * g4.x + wp.y * g4.y) + (wp.z * g4.z + wp.w * g4.w);
            #pragma unroll
            for (int off = 16; off; off >>= 1) {
                k1 += __shfl_xor_sync(~0u, k1, off);
                k2 += __shfl_xor_sync(~0u, k2, off);
            }
            if (lane == 0) { sK1[w] = k1; sK2[w] = k2; }
        }
    }
    __syncthreads();

    const int n0 = blockIdx.x * (THREADS * TOKPT) + tid;  // token t at n0 + t*THREADS
    const float* xT = g_xnT + n0;

    float2 accw[OT][TOKPT], accb[OT][TOKPT];
    #pragma unroll
    for (int o = 0; o < OT; o++)
        #pragma unroll
        for (int t = 0; t < TOKPT; t++) {
            accw[o][t] = make_float2(0.0f, 0.0f);
            accb[o][t] = make_float2(0.0f, 0.0f);
        }

    for (int dc = 0; dc < DIM / 4; dc++) {
        const float* p = xT + (size_t)(4 * dc) * NTOK;
        float2 xp[TOKPT][2];
        #pragma unroll
        for (int t = 0; t < TOKPT; t++) {
            const float* pt = p + t * THREADS;
            xp[t][0] = make_float2(pt[0],        pt[NTOK]);
            xp[t][1] = make_float2(pt[2 * NTOK], pt[3 * NTOK]);
        }

        #pragma unroll
        for (int o = 0; o < OT; o++) {
            float4 T4 = sT [o][dc];
            float4 A4 = sA [o][dc];
            float4 P4 = sCP[o][dc];
            float4 W4 = sW [o][dc];
            float2 Tl = make_float2(T4.x, T4.y), Th = make_float2(T4.z, T4.w);
            float2 Al = make_float2(A4.x, A4.y), Ah = make_float2(A4.z, A4.w);
            float2 Pl = make_float2(P4.x, P4.y), Ph = make_float2(P4.z, P4.w);
            float2 Wl = make_float2(W4.x, W4.y), Wh = make_float2(W4.z, W4.w);
            #pragma unroll
            for (int t = 0; t < TOKPT; t++) {
                {
                    float2 y = fadd2(xp[t][0], Tl);
                    float2 q = fmul2(y, y);
                    float2 m = ffma2(q, Al, H2);
                    float2 e = make_float2(ex2f(m.x), ex2f(m.y));
                    float2 g = fmul2(m, e);
                    accw[o][t] = ffma2(g, Pl, accw[o][t]);
                }
                {
                    float2 y = fadd2(xp[t][1], Th);
                    float2 q = fmul2(y, y);
                    float2 m = ffma2(q, Ah, H2);
                    float2 e = make_float2(ex2f(m.x), ex2f(m.y));
                    float2 g = fmul2(m, e);
                    accw[o][t] = ffma2(g, Ph, accw[o][t]);
                }
                accb[o][t] = ffma2(xp[t][0], Wl, accb[o][t]);
                accb[o][t] = ffma2(xp[t][1], Wh, accb[o][t]);
            }
        }
    }

    // ---- epilogue: float2 store per token ----
    #pragma unroll
    for (int t = 0; t < TOKPT; t++) {
        int n = n0 + t * THREADS;
        float2 ms = g_musv[n];
        float* op = out + (size_t)n * ODIM + o0;
        float2 res;
        #pragma unroll
        for (int j = 0; j < 2; j++) {
            float ac = accb[j][t].x + accb[j][t].y;
            float b = fmaf(ms.y, ac - sK1[j], ms.x * sK2[j]);
            float e = ex2f(-1.44269504f * b);
            float sig = __frcp_rn(1.0f + e);
            ((float*)&res)[j] = fmaf(b, sig, accw[j][t].x + accw[j][t].y);
        }
        ((float2*)op)[0] = res;
    }
}

extern "C" void kernel_launch(void* const* d_in, const int* in_sizes, int n_in,
                              void* d_out, int out_size) {
    const float* x     = (const float*)d_in[0];
    const float* scale = (const float*)d_in[1];
    const float* trans = (const float*)d_in[2];
    const float* ww    = (const float*)d_in[3];
    const float* bw    = (const float*)d_in[4];
    const float* gamma = (const float*)d_in[5];
    const float* beta  = (const float*)d_in[6];
    float* out = (float*)d_out;

    ln_kernel<<<NTOK / 8, 256>>>(x, gamma, beta);
    dim3 grid(NTOK / (THREADS * TOKPT), ODIM / OT);
    wave_kernel<<<grid, THREADS>>>(scale, trans, ww, bw, gamma, beta, out);
}

// round 14
// speedup vs baseline: 1.3212x; 1.3212x over previous
#include <cuda_runtime.h>

#define NTOK 8192
#define DIM 128
#define ODIM 128
#define THREADS 256
#define OT 4
#define TOKPT 4

typedef unsigned long long u64;

__device__ float g_xnT[DIM * NTOK];   // transposed: [d][n]
__device__ float2 g_musv[NTOK];

__device__ __forceinline__ float2 ffma2(float2 a, float2 b, float2 c) {
    float2 d;
    asm("fma.rn.f32x2 %0, %1, %2, %3;"
        : "=l"(reinterpret_cast<u64&>(d))
        : "l"(reinterpret_cast<u64 const&>(a)),
          "l"(reinterpret_cast<u64 const&>(b)),
          "l"(reinterpret_cast<u64 const&>(c)));
    return d;
}
__device__ __forceinline__ float2 fmul2(float2 a, float2 b) {
    float2 d;
    asm("mul.rn.f32x2 %0, %1, %2;"
        : "=l"(reinterpret_cast<u64&>(d))
        : "l"(reinterpret_cast<u64 const&>(a)),
          "l"(reinterpret_cast<u64 const&>(b)));
    return d;
}
__device__ __forceinline__ float2 fadd2(float2 a, float2 b) {
    float2 d;
    asm("add.rn.f32x2 %0, %1, %2;"
        : "=l"(reinterpret_cast<u64&>(d))
        : "l"(reinterpret_cast<u64 const&>(a)),
          "l"(reinterpret_cast<u64 const&>(b)));
    return d;
}
__device__ __forceinline__ float ex2f(float a) {
    float r; asm("ex2.approx.ftz.f32 %0, %1;" : "=f"(r) : "f"(a)); return r;
}

// ---------------- Kernel 1: LayerNorm + transpose (warp per token) ----------------
__global__ void ln_kernel(const float* __restrict__ x,
                          const float* __restrict__ gamma,
                          const float* __restrict__ beta) {
    __shared__ float sX[8][DIM];
    const int tok0 = blockIdx.x * 8;
    const int w = threadIdx.x >> 5;
    const int lane = threadIdx.x & 31;
    const int token = tok0 + w;

    float4 v = ((const float4*)(x + (size_t)token * DIM))[lane];
    float s = (v.x + v.y) + (v.z + v.w);
    #pragma unroll
    for (int off = 16; off; off >>= 1) s += __shfl_xor_sync(~0u, s, off);
    float mu = s * (1.0f / DIM);
    float dx = v.x - mu, dy = v.y - mu, dz = v.z - mu, dw = v.w - mu;
    float q = (dx * dx + dy * dy) + (dz * dz + dw * dw);
    #pragma unroll
    for (int off = 16; off; off >>= 1) q += __shfl_xor_sync(~0u, q, off);
    float ve = q * (1.0f / DIM) + 1e-5f;
    float r = rsqrtf(ve);
    float4 g = ((const float4*)gamma)[lane];
    float4 b = ((const float4*)beta)[lane];
    float4 o;
    o.x = fmaf(dx * r, g.x, b.x);
    o.y = fmaf(dy * r, g.y, b.y);
    o.z = fmaf(dz * r, g.z, b.z);
    o.w = fmaf(dw * r, g.w, b.w);
    ((float4*)&sX[w][0])[lane] = o;
    if (lane == 0) g_musv[token] = make_float2(mu, ve * r);
    __syncthreads();

    const int d = threadIdx.x >> 1;
    const int h = threadIdx.x & 1;
    float4 val;
    val.x = sX[4 * h + 0][d];
    val.y = sX[4 * h + 1][d];
    val.z = sX[4 * h + 2][d];
    val.w = sX[4 * h + 3][d];
    *((float4*)(g_xnT + (size_t)d * NTOK + tok0 + 4 * h)) = val;
}

// ---------------- Kernel 2: fused wavelet + base, x-prefetch double-buffer ----------------
// T-form: y = xn + T (T=-t), m = H + a*y^2 (a=-H/s^2, H=1/(2 ln2))
//   wavelet contribution = CP * m * 2^m,  CP = -C*ww/(H*2^H) = -0.7292730*ww
// base in xn-domain: b_o = sv*(acc_o - K1_o) + mu*K2_o  (W'=bw/gamma)
__global__ __launch_bounds__(THREADS, 2)
void wave_kernel(const float* __restrict__ scale,
                 const float* __restrict__ trans,
                 const float* __restrict__ ww,
                 const float* __restrict__ bw,
                 const float* __restrict__ gamma,
                 const float* __restrict__ beta,
                 float* __restrict__ out) {
    __shared__ float4 sT [OT][DIM / 4];
    __shared__ float4 sA [OT][DIM / 4];
    __shared__ float4 sCP[OT][DIM / 4];
    __shared__ float4 sW [OT][DIM / 4];
    __shared__ float  sK1[OT], sK2[OT];

    const int o0 = blockIdx.y * OT;
    const int tid = threadIdx.x;
    const float H = 0.72134752f;
    const float2 H2 = make_float2(H, H);

    // ---- fold params (OT*DIM = 512 elements) ----
    #pragma unroll
    for (int k = 0; k < (OT * DIM) / THREADS; k++) {
        int i = tid + k * THREADS;
        int gi = o0 * DIM + i;
        int d = i & (DIM - 1);
        float sc = scale[gi];
        float sp = (sc > 20.0f) ? sc : log1pf(expf(sc));
        float s = sp + 0.1f;
        ((float*)sT)[i]  = -trans[gi];
        ((float*)sA)[i]  = -H / (s * s);
        ((float*)sCP)[i] = -0.7292730f * ww[gi];
        ((float*)sW)[i]  = bw[gi] / gamma[d];
    }
    __syncthreads();

    // ---- K1, K2 per o: warp w (w < OT) reduces o=w ----
    {
        int w = tid >> 5, lane = tid & 31;
        if (w < OT) {
            float4 wp = sW[w][lane];
            float4 g4 = ((const float4*)gamma)[lane];
            float4 b4 = ((const float4*)beta)[lane];
            float k1 = (wp.x * b4.x + wp.y * b4.y) + (wp.z * b4.z + wp.w * b4.w);
            float k2 = (wp.x * g4.x + wp.y * g4.y) + (wp.z * g4.z + wp.w * g4.w);
            #pragma unroll
            for (int off = 16; off; off >>= 1) {
                k1 += __shfl_xor_sync(~0u, k1, off);
                k2 += __shfl_xor_sync(~0u, k2, off);
            }
            if (lane == 0) { sK1[w] = k1; sK2[w] = k2; }
        }
    }
    __syncthreads();

    const int n0 = blockIdx.x * (THREADS * TOKPT) + tid;  // token t at n0 + t*THREADS
    const float* xT = g_xnT + n0;

    float2 accw[OT][TOKPT], accb[OT][TOKPT];
    #pragma unroll
    for (int o = 0; o < OT; o++)
        #pragma unroll
        for (int t = 0; t < TOKPT; t++) {
            accw[o][t] = make_float2(0.0f, 0.0f);
            accb[o][t] = make_float2(0.0f, 0.0f);
        }

    // double-buffered x registers: xp[buf][token][d-pair]
    float2 xp[2][TOKPT][2];
    #pragma unroll
    for (int t = 0; t < TOKPT; t++) {
        const float* pt = xT + t * THREADS;
        xp[0][t][0] = make_float2(pt[0],        pt[NTOK]);
        xp[0][t][1] = make_float2(pt[2 * NTOK], pt[3 * NTOK]);
    }

    #pragma unroll 2
    for (int dc = 0; dc < DIM / 4; dc++) {
        const int cur = dc & 1, nxt = cur ^ 1;
        // prefetch next dc's x (wraps to dc=0 on last iter; harmless in-bounds)
        {
            const float* pn = xT + (size_t)(4 * ((dc + 1) & (DIM / 4 - 1))) * NTOK;
            #pragma unroll
            for (int t = 0; t < TOKPT; t++) {
                const float* pt = pn + t * THREADS;
                xp[nxt][t][0] = make_float2(pt[0],        pt[NTOK]);
                xp[nxt][t][1] = make_float2(pt[2 * NTOK], pt[3 * NTOK]);
            }
        }

        #pragma unroll
        for (int o = 0; o < OT; o++) {
            float4 T4 = sT [o][dc];
            float4 A4 = sA [o][dc];
            float4 P4 = sCP[o][dc];
            float4 W4 = sW [o][dc];
            float2 Tl = make_float2(T4.x, T4.y), Th = make_float2(T4.z, T4.w);
            float2 Al = make_float2(A4.x, A4.y), Ah = make_float2(A4.z, A4.w);
            float2 Pl = make_float2(P4.x, P4.y), Ph = make_float2(P4.z, P4.w);
            float2 Wl = make_float2(W4.x, W4.y), Wh = make_float2(W4.z, W4.w);
            #pragma unroll
            for (int t = 0; t < TOKPT; t++) {
                {
                    float2 y = fadd2(xp[cur][t][0], Tl);
                    float2 q = fmul2(y, y);
                    float2 m = ffma2(q, Al, H2);
                    float2 e = make_float2(ex2f(m.x), ex2f(m.y));
                    float2 g = fmul2(m, e);
                    accw[o][t] = ffma2(g, Pl, accw[o][t]);
                }
                {
                    float2 y = fadd2(xp[cur][t][1], Th);
                    float2 q = fmul2(y, y);
                    float2 m = ffma2(q, Ah, H2);
                    float2 e = make_float2(ex2f(m.x), ex2f(m.y));
                    float2 g = fmul2(m, e);
                    accw[o][t] = ffma2(g, Ph, accw[o][t]);
                }
                accb[o][t] = ffma2(xp[cur][t][0], Wl, accb[o][t]);
                accb[o][t] = ffma2(xp[cur][t][1], Wh, accb[o][t]);
            }
        }
    }

    // ---- epilogue ----
    #pragma unroll
    for (int t = 0; t < TOKPT; t++) {
        int n = n0 + t * THREADS;
        float2 ms = g_musv[n];
        float* op = out + (size_t)n * ODIM + o0;
        float4 res;
        float* rp = (float*)&res;
        #pragma unroll
        for (int j = 0; j < 4; j++) {
            float ac = accb[j][t].x + accb[j][t].y;
            float b = fmaf(ms.y, ac - sK1[j], ms.x * sK2[j]);
            float e = ex2f(-1.44269504f * b);
            float sig = __frcp_rn(1.0f + e);
            rp[j] = fmaf(b, sig, accw[j][t].x + accw[j][t].y);
        }
        ((float4*)op)[0] = res;
    }
}

extern "C" void kernel_launch(void* const* d_in, const int* in_sizes, int n_in,
                              void* d_out, int out_size) {
    const float* x     = (const float*)d_in[0];
    const float* scale = (const float*)d_in[1];
    const float* trans = (const float*)d_in[2];
    const float* ww    = (const float*)d_in[3];
    const float* bw    = (const float*)d_in[4];
    const float* gamma = (const float*)d_in[5];
    const float* beta  = (const float*)d_in[6];
    float* out = (float*)d_out;

    ln_kernel<<<NTOK / 8, 256>>>(x, gamma, beta);
    dim3 grid(NTOK / (THREADS * TOKPT), ODIM / OT);
    wave_kernel<<<grid, THREADS>>>(scale, trans, ww, bw, gamma, beta, out);
}